// round 1
// baseline (speedup 1.0000x reference)
#include <cuda_runtime.h>
#include <math.h>

#define BB 32
#define SS 196
#define TT 64
#define HH 1024
#define VV 32000

// ---------------- device scratch (no allocation allowed) ----------------
__device__ float g_hbuf[2][BB * HH];
__device__ float g_cbuf[2][BB * HH];
__device__ float g_q[BB * HH];
__device__ float g_sc[BB * SS];             // raw attention scores
__device__ float g_ctx[BB * HH];
__device__ float g_Hall[BB * TT * HH];      // h_t for all steps, [b][t][h]

// ---------------- init: zero h0, c0 ----------------
__global__ void k_init() {
    int i = blockIdx.x * blockDim.x + threadIdx.x;
    if (i < BB * HH) {
        g_hbuf[0][i] = 0.f;
        g_cbuf[0][i] = 0.f;
    }
}

// ---------------- q = h @ attn_W.T   (grid: (H/8, B), 256 thr) ----------------
__global__ void k_attn_q(const float* __restrict__ attn_W, int p) {
    int b = blockIdx.y;
    __shared__ float hs[HH];
    const float* h = &g_hbuf[p][b * HH];
    for (int i = threadIdx.x; i < HH; i += blockDim.x) hs[i] = h[i];
    __syncthreads();
    int warp = threadIdx.x >> 5, lane = threadIdx.x & 31;
    int j = blockIdx.x * 8 + warp;
    const float* wr = attn_W + (size_t)j * HH;
    float acc = 0.f;
#pragma unroll 8
    for (int k = lane; k < HH; k += 32) acc += hs[k] * wr[k];
#pragma unroll
    for (int o = 16; o > 0; o >>= 1) acc += __shfl_xor_sync(0xffffffffu, acc, o);
    if (lane == 0) g_q[b * HH + j] = acc;
}

// ---------------- scores[b][s] = q[b] . memory[b][s]  (grid: (25, B), 256 thr) ----------------
__global__ void k_scores(const float* __restrict__ memory) {
    int b = blockIdx.y;
    __shared__ float qs[HH];
    const float* q = &g_q[b * HH];
    for (int i = threadIdx.x; i < HH; i += blockDim.x) qs[i] = q[i];
    __syncthreads();
    int warp = threadIdx.x >> 5, lane = threadIdx.x & 31;
    int s = blockIdx.x * 8 + warp;
    if (s >= SS) return;
    const float* mr = memory + ((size_t)b * SS + s) * HH;
    float acc = 0.f;
#pragma unroll 8
    for (int k = lane; k < HH; k += 32) acc += qs[k] * mr[k];
#pragma unroll
    for (int o = 16; o > 0; o >>= 1) acc += __shfl_xor_sync(0xffffffffu, acc, o);
    if (lane == 0) g_sc[b * SS + s] = acc;
}

// ---------------- softmax + ctx  (grid: (H/128, B), 128 thr) ----------------
__global__ void k_ctx(const float* __restrict__ memory) {
    int b = blockIdx.y;
    int tid = threadIdx.x;
    __shared__ float w[SS];
    __shared__ float red[128];

    float lmax = -1e30f;
    for (int s = tid; s < SS; s += 128) {
        float v = g_sc[b * SS + s];
        w[s] = v;
        lmax = fmaxf(lmax, v);
    }
    red[tid] = lmax;
    __syncthreads();
    for (int o = 64; o > 0; o >>= 1) {
        if (tid < o) red[tid] = fmaxf(red[tid], red[tid + o]);
        __syncthreads();
    }
    float mx = red[0];
    __syncthreads();

    float lsum = 0.f;
    for (int s = tid; s < SS; s += 128) {
        float e = expf(w[s] - mx);
        w[s] = e;
        lsum += e;
    }
    red[tid] = lsum;
    __syncthreads();
    for (int o = 64; o > 0; o >>= 1) {
        if (tid < o) red[tid] += red[tid + o];
        __syncthreads();
    }
    float inv = 1.f / red[0];

    int hcol = blockIdx.x * 128 + tid;
    const float* mb = memory + (size_t)b * SS * HH + hcol;
    float acc = 0.f;
#pragma unroll 4
    for (int s = 0; s < SS; s++) acc += w[s] * mb[(size_t)s * HH];
    g_ctx[b * HH + hcol] = acc * inv;
}

// ---------------- gates + LSTM cell  (grid: (H/8, B), 256 thr) ----------------
__device__ __forceinline__ float sigmoidf_(float x) { return 1.f / (1.f + expf(-x)); }

__global__ void k_gates(const int* __restrict__ captions,
                        const float* __restrict__ emb_table,
                        const float* __restrict__ W_ih,
                        const float* __restrict__ W_hh,
                        const float* __restrict__ b_ih,
                        const float* __restrict__ b_hh,
                        int t, int p) {
    int b = blockIdx.y;
    __shared__ float es[HH];
    __shared__ float cs[HH];
    __shared__ float hs[HH];

    int cap = captions[b * TT + t];
    const float* erow = emb_table + (size_t)cap * HH;
    const float* hrow = &g_hbuf[p][b * HH];
    const float* crow = &g_ctx[b * HH];
    for (int i = threadIdx.x; i < HH; i += blockDim.x) {
        es[i] = erow[i];
        cs[i] = crow[i];
        hs[i] = hrow[i];
    }
    __syncthreads();

    int warp = threadIdx.x >> 5, lane = threadIdx.x & 31;
    int j = blockIdx.x * 8 + warp;

    const float* wi0 = W_ih + (size_t)(0 * HH + j) * (2 * HH);
    const float* wi1 = W_ih + (size_t)(1 * HH + j) * (2 * HH);
    const float* wi2 = W_ih + (size_t)(2 * HH + j) * (2 * HH);
    const float* wi3 = W_ih + (size_t)(3 * HH + j) * (2 * HH);
    const float* wh0 = W_hh + (size_t)(0 * HH + j) * HH;
    const float* wh1 = W_hh + (size_t)(1 * HH + j) * HH;
    const float* wh2 = W_hh + (size_t)(2 * HH + j) * HH;
    const float* wh3 = W_hh + (size_t)(3 * HH + j) * HH;

    float a0 = 0.f, a1 = 0.f, a2 = 0.f, a3 = 0.f;
#pragma unroll 4
    for (int k = lane; k < HH; k += 32) {
        float e = es[k], c = cs[k], hv = hs[k];
        a0 += e * wi0[k] + c * wi0[HH + k] + hv * wh0[k];
        a1 += e * wi1[k] + c * wi1[HH + k] + hv * wh1[k];
        a2 += e * wi2[k] + c * wi2[HH + k] + hv * wh2[k];
        a3 += e * wi3[k] + c * wi3[HH + k] + hv * wh3[k];
    }
#pragma unroll
    for (int o = 16; o > 0; o >>= 1) {
        a0 += __shfl_xor_sync(0xffffffffu, a0, o);
        a1 += __shfl_xor_sync(0xffffffffu, a1, o);
        a2 += __shfl_xor_sync(0xffffffffu, a2, o);
        a3 += __shfl_xor_sync(0xffffffffu, a3, o);
    }
    if (lane == 0) {
        float gi = sigmoidf_(a0 + b_ih[j] + b_hh[j]);
        float gf = sigmoidf_(a1 + b_ih[HH + j] + b_hh[HH + j]);
        float gg = tanhf(a2 + b_ih[2 * HH + j] + b_hh[2 * HH + j]);
        float go = sigmoidf_(a3 + b_ih[3 * HH + j] + b_hh[3 * HH + j]);
        float cprev = g_cbuf[p][b * HH + j];
        float cn = gf * cprev + gi * gg;
        float hn = go * tanhf(cn);
        g_cbuf[p ^ 1][b * HH + j] = cn;
        g_hbuf[p ^ 1][b * HH + j] = hn;
        g_Hall[((size_t)b * TT + t) * HH + j] = hn;
    }
}

// ---------------- logits = Hall @ W_out.T + b_out  (M=2048,N=32000,K=1024) ----------------
// 128x128 tile, BK=8, 256 threads, 8x8 per thread.
#define GBM 128
#define GBN 128
#define GBK 8

__global__ __launch_bounds__(256, 2) void k_logits(const float* __restrict__ Wout,
                                                   const float* __restrict__ bout,
                                                   float* __restrict__ out) {
    __shared__ float As[GBK][GBM];
    __shared__ float Bs[GBK][GBN];
    int bm = blockIdx.x;   // 0..15   (fast dim -> 16 consecutive blocks reuse same W_out tile)
    int bn = blockIdx.y;   // 0..249
    const float* A = g_Hall + (size_t)bm * GBM * HH;
    const float* Bt = Wout + (size_t)bn * GBN * HH;

    int tid = threadIdx.x;
    int l_row = tid >> 1;            // 0..127
    int l_col = (tid & 1) * 4;       // 0 or 4
    int tx = tid & 15;               // n-dir thread
    int ty = tid >> 4;               // m-dir thread

    float acc[8][8];
#pragma unroll
    for (int i = 0; i < 8; i++)
#pragma unroll
        for (int jj = 0; jj < 8; jj++) acc[i][jj] = 0.f;

    for (int k0 = 0; k0 < HH; k0 += GBK) {
        float4 av = *(const float4*)(A + (size_t)l_row * HH + k0 + l_col);
        As[l_col + 0][l_row] = av.x;
        As[l_col + 1][l_row] = av.y;
        As[l_col + 2][l_row] = av.z;
        As[l_col + 3][l_row] = av.w;
        float4 bv = *(const float4*)(Bt + (size_t)l_row * HH + k0 + l_col);
        Bs[l_col + 0][l_row] = bv.x;
        Bs[l_col + 1][l_row] = bv.y;
        Bs[l_col + 2][l_row] = bv.z;
        Bs[l_col + 3][l_row] = bv.w;
        __syncthreads();

#pragma unroll
        for (int kk = 0; kk < GBK; kk++) {
            float ar[8], br[8];
#pragma unroll
            for (int i = 0; i < 8; i++) ar[i] = As[kk][ty * 8 + i];
#pragma unroll
            for (int jj = 0; jj < 8; jj++) br[jj] = Bs[kk][tx * 8 + jj];
#pragma unroll
            for (int i = 0; i < 8; i++)
#pragma unroll
                for (int jj = 0; jj < 8; jj++) acc[i][jj] += ar[i] * br[jj];
        }
        __syncthreads();
    }

#pragma unroll
    for (int i = 0; i < 8; i++) {
        int m = bm * GBM + ty * 8 + i;
#pragma unroll
        for (int jj = 0; jj < 8; jj++) {
            int n = bn * GBN + tx * 8 + jj;
            out[(size_t)m * VV + n] = acc[i][jj] + bout[n];
        }
    }
}

// ---------------- copy final h, c ----------------
__global__ void k_final(float* __restrict__ out) {
    int i = blockIdx.x * blockDim.x + threadIdx.x;
    if (i < BB * HH) {
        size_t base = (size_t)BB * TT * VV;
        out[base + i] = g_hbuf[0][i];               // T=64 even -> final state in buf 0
        out[base + BB * HH + i] = g_cbuf[0][i];
    }
}

// ---------------- launch ----------------
extern "C" void kernel_launch(void* const* d_in, const int* in_sizes, int n_in,
                              void* d_out, int out_size) {
    const float* memory    = (const float*)d_in[0];
    const int*   captions  = (const int*)d_in[1];
    const float* emb_table = (const float*)d_in[2];
    const float* attn_W    = (const float*)d_in[3];
    const float* W_ih      = (const float*)d_in[4];
    const float* W_hh      = (const float*)d_in[5];
    const float* b_ih      = (const float*)d_in[6];
    const float* b_hh      = (const float*)d_in[7];
    const float* W_out     = (const float*)d_in[8];
    const float* b_out     = (const float*)d_in[9];
    float* out = (float*)d_out;

    k_init<<<(BB * HH + 255) / 256, 256>>>();

    for (int t = 0; t < TT; t++) {
        int p = t & 1;
        k_attn_q<<<dim3(HH / 8, BB), 256>>>(attn_W, p);
        k_scores<<<dim3((SS + 7) / 8, BB), 256>>>(memory);
        k_ctx<<<dim3(HH / 128, BB), 128>>>(memory);
        k_gates<<<dim3(HH / 8, BB), 256>>>(captions, emb_table, W_ih, W_hh, b_ih, b_hh, t, p);
    }

    k_logits<<<dim3((BB * TT) / GBM, VV / GBN), 256>>>(W_out, b_out, out);
    k_final<<<(BB * HH + 255) / 256, 256>>>(out);
}

// round 2
// speedup vs baseline: 1.8968x; 1.8968x over previous
#include <cuda_runtime.h>
#include <math.h>

#define BB 32
#define SS 196
#define TT 64
#define HH 1024
#define VV 32000

// ---------------- device scratch ----------------
__device__ float g_hbuf[2][BB * HH];
__device__ float g_cbuf[2][BB * HH];
__device__ float g_qpart[8][BB * HH];
__device__ float g_q[BB * HH];
__device__ float g_sc[BB * SS];
__device__ float g_ctx[BB * HH];
__device__ float g_gpart[4][BB * 4 * HH];
__device__ float g_P[(size_t)BB * TT * 4 * HH];   // 32 MB: emb @ W_ih[:, :H].T + biases
__device__ float g_Hall[BB * TT * HH];

__device__ __forceinline__ float sigmoidf_(float x) { return 1.f / (1.f + expf(-x)); }

// ---------------- init ----------------
__global__ void k_init() {
    int i = blockIdx.x * blockDim.x + threadIdx.x;
    if (i < BB * HH) { g_hbuf[0][i] = 0.f; g_cbuf[0][i] = 0.f; }
}

// ============ P = emb @ W_ih[:, 0:H].T + b_ih + b_hh  (M=2048, N=4096, K=1024) ============
#define GBM 128
#define GBN 128
#define GBK 8

__global__ __launch_bounds__(256, 2) void k_embW(const int* __restrict__ captions,
                                                 const float* __restrict__ emb_table,
                                                 const float* __restrict__ W_ih,
                                                 const float* __restrict__ b_ih,
                                                 const float* __restrict__ b_hh) {
    __shared__ float As[GBK][GBM];
    __shared__ float Bs[GBK][GBN];
    int bm = blockIdx.x;   // 16
    int bn = blockIdx.y;   // 32

    int tid = threadIdx.x;
    int l_row = tid >> 1;
    int l_col = (tid & 1) * 4;
    int tx = tid & 15;
    int ty = tid >> 4;

    int cap = captions[bm * GBM + l_row];
    const float* Arow = emb_table + (size_t)cap * HH;
    const float* Brow = W_ih + (size_t)(bn * GBN + l_row) * (2 * HH);  // K range = [0, HH)

    float acc[8][8];
#pragma unroll
    for (int i = 0; i < 8; i++)
#pragma unroll
        for (int jj = 0; jj < 8; jj++) acc[i][jj] = 0.f;

    for (int k0 = 0; k0 < HH; k0 += GBK) {
        float4 av = *(const float4*)(Arow + k0 + l_col);
        As[l_col + 0][l_row] = av.x; As[l_col + 1][l_row] = av.y;
        As[l_col + 2][l_row] = av.z; As[l_col + 3][l_row] = av.w;
        float4 bv = *(const float4*)(Brow + k0 + l_col);
        Bs[l_col + 0][l_row] = bv.x; Bs[l_col + 1][l_row] = bv.y;
        Bs[l_col + 2][l_row] = bv.z; Bs[l_col + 3][l_row] = bv.w;
        __syncthreads();
#pragma unroll
        for (int kk = 0; kk < GBK; kk++) {
            float ar[8], br[8];
#pragma unroll
            for (int i = 0; i < 8; i++) ar[i] = As[kk][ty * 8 + i];
#pragma unroll
            for (int jj = 0; jj < 8; jj++) br[jj] = Bs[kk][tx * 8 + jj];
#pragma unroll
            for (int i = 0; i < 8; i++)
#pragma unroll
                for (int jj = 0; jj < 8; jj++) acc[i][jj] += ar[i] * br[jj];
        }
        __syncthreads();
    }
#pragma unroll
    for (int i = 0; i < 8; i++) {
        int m = bm * GBM + ty * 8 + i;
#pragma unroll
        for (int jj = 0; jj < 8; jj++) {
            int n = bn * GBN + tx * 8 + jj;
            g_P[(size_t)m * (4 * HH) + n] = acc[i][jj] + b_ih[n] + b_hh[n];
        }
    }
}

// ============ q partial: [32 x 1024] = h @ attn_W.T, k-split 8 ============
// grid (16 ntiles of 64 j, 8 ksplit), 128 thr (4 warps x 16 j). lane = b.
__global__ void k_q(const float* __restrict__ attn_W, int p) {
    int nt = blockIdx.x, ks = blockIdx.y;
    int kbeg = ks * 128;
    int tid = threadIdx.x, warp = tid >> 5, lane = tid & 31;
    __shared__ float xs[32][33];
    __shared__ float ws[32][68];
    float acc[16];
#pragma unroll
    for (int i = 0; i < 16; i++) acc[i] = 0.f;
    int jbase = nt * 64;

    for (int k0 = 0; k0 < 128; k0 += 32) {
        for (int i = tid; i < 1024; i += 128) {
            int m = i >> 5, kk = i & 31;
            xs[m][kk] = g_hbuf[p][m * HH + kbeg + k0 + kk];
        }
        for (int i = tid; i < 512; i += 128) {
            int j = i >> 3, k4 = (i & 7) * 4;
            float4 v = *(const float4*)(attn_W + (size_t)(jbase + j) * HH + kbeg + k0 + k4);
            ws[k4 + 0][j] = v.x; ws[k4 + 1][j] = v.y; ws[k4 + 2][j] = v.z; ws[k4 + 3][j] = v.w;
        }
        __syncthreads();
#pragma unroll
        for (int kk = 0; kk < 32; kk++) {
            float xv = xs[lane][kk];
            float4 w0 = *(const float4*)&ws[kk][warp * 16 + 0];
            float4 w1 = *(const float4*)&ws[kk][warp * 16 + 4];
            float4 w2 = *(const float4*)&ws[kk][warp * 16 + 8];
            float4 w3 = *(const float4*)&ws[kk][warp * 16 + 12];
            acc[0] += xv * w0.x; acc[1] += xv * w0.y; acc[2] += xv * w0.z; acc[3] += xv * w0.w;
            acc[4] += xv * w1.x; acc[5] += xv * w1.y; acc[6] += xv * w1.z; acc[7] += xv * w1.w;
            acc[8] += xv * w2.x; acc[9] += xv * w2.y; acc[10] += xv * w2.z; acc[11] += xv * w2.w;
            acc[12] += xv * w3.x; acc[13] += xv * w3.y; acc[14] += xv * w3.z; acc[15] += xv * w3.w;
        }
        __syncthreads();
    }
#pragma unroll
    for (int jj = 0; jj < 16; jj++)
        g_qpart[ks][lane * HH + jbase + warp * 16 + jj] = acc[jj];
}

// ============ reduce q partials ============
__global__ void k_qred() {
    int i = blockIdx.x * blockDim.x + threadIdx.x;  // 32768
    float s = 0.f;
#pragma unroll
    for (int ks = 0; ks < 8; ks++) s += g_qpart[ks][i];
    g_q[i] = s;
}

// ============ scores ============
// grid (49, B), 128 thr: warp -> one s
__global__ void k_scores(const float* __restrict__ memory) {
    int b = blockIdx.y;
    int tid = threadIdx.x, warp = tid >> 5, lane = tid & 31;
    __shared__ float qs[HH];
    for (int i = tid; i < HH; i += 128) qs[i] = g_q[b * HH + i];
    __syncthreads();
    int s = blockIdx.x * 4 + warp;
    const float* mr = memory + ((size_t)b * SS + s) * HH;
    float a0 = 0.f, a1 = 0.f, a2 = 0.f, a3 = 0.f;
#pragma unroll 2
    for (int k0 = 0; k0 < HH; k0 += 128) {
        float m0 = mr[k0 + lane], m1 = mr[k0 + 32 + lane];
        float m2 = mr[k0 + 64 + lane], m3 = mr[k0 + 96 + lane];
        a0 += qs[k0 + lane] * m0;
        a1 += qs[k0 + 32 + lane] * m1;
        a2 += qs[k0 + 64 + lane] * m2;
        a3 += qs[k0 + 96 + lane] * m3;
    }
    float acc = a0 + a1 + a2 + a3;
#pragma unroll
    for (int o = 16; o > 0; o >>= 1) acc += __shfl_xor_sync(0xffffffffu, acc, o);
    if (lane == 0) g_sc[b * SS + s] = acc;
}

// ============ softmax (recomputed per block) + ctx ============
// grid (4, B), 256 thr: thread -> one hcol
__global__ void k_ctx2(const float* __restrict__ memory) {
    int b = blockIdx.y;
    int tid = threadIdx.x;
    __shared__ float w[SS];
    __shared__ float red[256];

    float v = (tid < SS) ? g_sc[b * SS + tid] : -1e30f;
    red[tid] = v;
    __syncthreads();
    for (int o = 128; o > 0; o >>= 1) {
        if (tid < o) red[tid] = fmaxf(red[tid], red[tid + o]);
        __syncthreads();
    }
    float mx = red[0];
    __syncthreads();
    float e = (tid < SS) ? expf(v - mx) : 0.f;
    if (tid < SS) w[tid] = e;
    red[tid] = e;
    __syncthreads();
    for (int o = 128; o > 0; o >>= 1) {
        if (tid < o) red[tid] += red[tid + o];
        __syncthreads();
    }
    float inv = 1.f / red[0];
    __syncthreads();

    int hcol = blockIdx.x * 256 + tid;
    const float* mb = memory + (size_t)b * SS * HH + hcol;
    float a0 = 0.f, a1 = 0.f, a2 = 0.f, a3 = 0.f;
    int s = 0;
    for (; s + 8 <= SS; s += 8) {
        float m0 = mb[(size_t)(s + 0) * HH], m1 = mb[(size_t)(s + 1) * HH];
        float m2 = mb[(size_t)(s + 2) * HH], m3 = mb[(size_t)(s + 3) * HH];
        float m4 = mb[(size_t)(s + 4) * HH], m5 = mb[(size_t)(s + 5) * HH];
        float m6 = mb[(size_t)(s + 6) * HH], m7 = mb[(size_t)(s + 7) * HH];
        a0 += w[s + 0] * m0; a1 += w[s + 1] * m1; a2 += w[s + 2] * m2; a3 += w[s + 3] * m3;
        a0 += w[s + 4] * m4; a1 += w[s + 5] * m5; a2 += w[s + 6] * m6; a3 += w[s + 7] * m7;
    }
    {   // tail: 196 = 24*8 + 4
        float m0 = mb[(size_t)(s + 0) * HH], m1 = mb[(size_t)(s + 1) * HH];
        float m2 = mb[(size_t)(s + 2) * HH], m3 = mb[(size_t)(s + 3) * HH];
        a0 += w[s + 0] * m0; a1 += w[s + 1] * m1; a2 += w[s + 2] * m2; a3 += w[s + 3] * m3;
    }
    g_ctx[b * HH + hcol] = (a0 + a1 + a2 + a3) * inv;
}

// ============ gates partials: [32 x 4096] over K=2048 (ctx | h), k-split 4 ============
// grid (64 ntiles of 64 j, 4 ksplit), 128 thr. lane = b.
__global__ void k_gates_b(const float* __restrict__ W_ih,
                          const float* __restrict__ W_hh, int p) {
    int nt = blockIdx.x, ks = blockIdx.y;
    int kbeg = ks * 512;
    int tid = threadIdx.x, warp = tid >> 5, lane = tid & 31;
    __shared__ float xs[32][33];
    __shared__ float ws[32][68];

    const float* xbase;
    const float* wbase;
    int wstride;
    if (ks < 2) { xbase = g_ctx + kbeg;              wbase = W_ih + HH + kbeg; wstride = 2 * HH; }
    else        { xbase = g_hbuf[p] + (kbeg - HH);   wbase = W_hh + (kbeg - HH); wstride = HH; }

    float acc[16];
#pragma unroll
    for (int i = 0; i < 16; i++) acc[i] = 0.f;
    int jbase = nt * 64;

    for (int k0 = 0; k0 < 512; k0 += 32) {
        for (int i = tid; i < 1024; i += 128) {
            int m = i >> 5, kk = i & 31;
            xs[m][kk] = xbase[m * HH + k0 + kk];
        }
        for (int i = tid; i < 512; i += 128) {
            int j = i >> 3, k4 = (i & 7) * 4;
            float4 v = *(const float4*)(wbase + (size_t)(jbase + j) * wstride + k0 + k4);
            ws[k4 + 0][j] = v.x; ws[k4 + 1][j] = v.y; ws[k4 + 2][j] = v.z; ws[k4 + 3][j] = v.w;
        }
        __syncthreads();
#pragma unroll
        for (int kk = 0; kk < 32; kk++) {
            float xv = xs[lane][kk];
            float4 w0 = *(const float4*)&ws[kk][warp * 16 + 0];
            float4 w1 = *(const float4*)&ws[kk][warp * 16 + 4];
            float4 w2 = *(const float4*)&ws[kk][warp * 16 + 8];
            float4 w3 = *(const float4*)&ws[kk][warp * 16 + 12];
            acc[0] += xv * w0.x; acc[1] += xv * w0.y; acc[2] += xv * w0.z; acc[3] += xv * w0.w;
            acc[4] += xv * w1.x; acc[5] += xv * w1.y; acc[6] += xv * w1.z; acc[7] += xv * w1.w;
            acc[8] += xv * w2.x; acc[9] += xv * w2.y; acc[10] += xv * w2.z; acc[11] += xv * w2.w;
            acc[12] += xv * w3.x; acc[13] += xv * w3.y; acc[14] += xv * w3.z; acc[15] += xv * w3.w;
        }
        __syncthreads();
    }
#pragma unroll
    for (int jj = 0; jj < 16; jj++)
        g_gpart[ks][lane * (4 * HH) + jbase + warp * 16 + jj] = acc[jj];
}

// ============ LSTM cell: sum partials + P, activations, state update ============
__global__ void k_cell(int t, int p) {
    int i = blockIdx.x * blockDim.x + threadIdx.x;  // 32768
    int b = i >> 10, j = i & 1023;
    size_t pr = (size_t)(b * TT + t) * (4 * HH);
    float a0 = g_P[pr + j];
    float a1 = g_P[pr + j + HH];
    float a2 = g_P[pr + j + 2 * HH];
    float a3 = g_P[pr + j + 3 * HH];
#pragma unroll
    for (int ks = 0; ks < 4; ks++) {
        const float* gp = g_gpart[ks] + b * (4 * HH);
        a0 += gp[j];
        a1 += gp[j + HH];
        a2 += gp[j + 2 * HH];
        a3 += gp[j + 3 * HH];
    }
    float gi = sigmoidf_(a0);
    float gf = sigmoidf_(a1);
    float gg = tanhf(a2);
    float go = sigmoidf_(a3);
    float cp = g_cbuf[p][b * HH + j];
    float cn = gf * cp + gi * gg;
    float hn = go * tanhf(cn);
    g_cbuf[p ^ 1][b * HH + j] = cn;
    g_hbuf[p ^ 1][b * HH + j] = hn;
    g_Hall[(b * TT + t) * HH + j] = hn;
}

// ============ logits = Hall @ W_out.T + b_out (M=2048, N=32000, K=1024) ============
__global__ __launch_bounds__(256, 2) void k_logits(const float* __restrict__ Wout,
                                                   const float* __restrict__ bout,
                                                   float* __restrict__ out) {
    __shared__ float As[GBK][GBM];
    __shared__ float Bs[GBK][GBN];
    int bm = blockIdx.x;
    int bn = blockIdx.y;
    const float* A = g_Hall + (size_t)bm * GBM * HH;
    const float* Bt = Wout + (size_t)bn * GBN * HH;

    int tid = threadIdx.x;
    int l_row = tid >> 1;
    int l_col = (tid & 1) * 4;
    int tx = tid & 15;
    int ty = tid >> 4;

    float acc[8][8];
#pragma unroll
    for (int i = 0; i < 8; i++)
#pragma unroll
        for (int jj = 0; jj < 8; jj++) acc[i][jj] = 0.f;

    for (int k0 = 0; k0 < HH; k0 += GBK) {
        float4 av = *(const float4*)(A + (size_t)l_row * HH + k0 + l_col);
        As[l_col + 0][l_row] = av.x; As[l_col + 1][l_row] = av.y;
        As[l_col + 2][l_row] = av.z; As[l_col + 3][l_row] = av.w;
        float4 bv = *(const float4*)(Bt + (size_t)l_row * HH + k0 + l_col);
        Bs[l_col + 0][l_row] = bv.x; Bs[l_col + 1][l_row] = bv.y;
        Bs[l_col + 2][l_row] = bv.z; Bs[l_col + 3][l_row] = bv.w;
        __syncthreads();
#pragma unroll
        for (int kk = 0; kk < GBK; kk++) {
            float ar[8], br[8];
#pragma unroll
            for (int i = 0; i < 8; i++) ar[i] = As[kk][ty * 8 + i];
#pragma unroll
            for (int jj = 0; jj < 8; jj++) br[jj] = Bs[kk][tx * 8 + jj];
#pragma unroll
            for (int i = 0; i < 8; i++)
#pragma unroll
                for (int jj = 0; jj < 8; jj++) acc[i][jj] += ar[i] * br[jj];
        }
        __syncthreads();
    }
#pragma unroll
    for (int i = 0; i < 8; i++) {
        int m = bm * GBM + ty * 8 + i;
#pragma unroll
        for (int jj = 0; jj < 8; jj++) {
            int n = bn * GBN + tx * 8 + jj;
            out[(size_t)m * VV + n] = acc[i][jj] + bout[n];
        }
    }
}

// ============ final h, c ============
__global__ void k_final(float* __restrict__ out) {
    int i = blockIdx.x * blockDim.x + threadIdx.x;
    if (i < BB * HH) {
        size_t base = (size_t)BB * TT * VV;
        out[base + i] = g_hbuf[0][i];
        out[base + BB * HH + i] = g_cbuf[0][i];
    }
}

// ---------------- launch ----------------
extern "C" void kernel_launch(void* const* d_in, const int* in_sizes, int n_in,
                              void* d_out, int out_size) {
    const float* memory    = (const float*)d_in[0];
    const int*   captions  = (const int*)d_in[1];
    const float* emb_table = (const float*)d_in[2];
    const float* attn_W    = (const float*)d_in[3];
    const float* W_ih      = (const float*)d_in[4];
    const float* W_hh      = (const float*)d_in[5];
    const float* b_ih      = (const float*)d_in[6];
    const float* b_hh      = (const float*)d_in[7];
    const float* W_out     = (const float*)d_in[8];
    const float* b_out     = (const float*)d_in[9];
    float* out = (float*)d_out;

    k_init<<<(BB * HH + 255) / 256, 256>>>();
    k_embW<<<dim3((BB * TT) / GBM, (4 * HH) / GBN), 256>>>(captions, emb_table, W_ih, b_ih, b_hh);

    for (int t = 0; t < TT; t++) {
        int p = t & 1;
        k_q<<<dim3(16, 8), 128>>>(attn_W, p);
        k_qred<<<128, 256>>>();
        k_scores<<<dim3(49, BB), 128>>>(memory);
        k_ctx2<<<dim3(4, BB), 256>>>(memory);
        k_gates_b<<<dim3(64, 4), 128>>>(W_ih, W_hh, p);
        k_cell<<<128, 256>>>(t, p);
    }

    k_logits<<<dim3((BB * TT) / GBM, VV / GBN), 256>>>(W_out, b_out, out);
    k_final<<<(BB * HH + 255) / 256, 256>>>(out);
}

// round 4
// speedup vs baseline: 2.3694x; 1.2492x over previous
#include <cuda_runtime.h>
#include <cuda_bf16.h>
#include <math.h>
#include <stdint.h>

#define BB 32
#define SS 196
#define TT 64
#define HH 1024
#define VV 32000

// ---------------- device scratch ----------------
__device__ float g_hbuf[2][BB * HH];
__device__ float g_cbuf[2][BB * HH];
__device__ float g_qpart[8][BB * HH];
__device__ float g_q[BB * HH];
__device__ float g_sc[BB * SS];
__device__ float g_ctx[BB * HH];
__device__ float g_gpart[4][BB * 4 * HH];
__device__ float g_P[(size_t)BB * TT * 4 * HH];
__device__ float g_Hall[BB * TT * HH];
// bf16 split operands for tensor-core logits
__device__ __nv_bfloat16 g_Wh[(size_t)VV * HH];
__device__ __nv_bfloat16 g_Wl[(size_t)VV * HH];
__device__ __nv_bfloat16 g_Ah[(size_t)BB * TT * HH];
__device__ __nv_bfloat16 g_Al[(size_t)BB * TT * HH];

__device__ __forceinline__ float sigmoidf_(float x) { return 1.f / (1.f + expf(-x)); }

__device__ __forceinline__ uint32_t smem_u32(const void* p) {
    uint32_t a;
    asm("{ .reg .u64 t; cvta.to.shared.u64 t, %1; cvt.u32.u64 %0, t; }" : "=r"(a) : "l"(p));
    return a;
}
__device__ __forceinline__ void cp16(uint32_t s, const void* g) {
    asm volatile("cp.async.cg.shared.global [%0], [%1], 16;" :: "r"(s), "l"(g));
}
__device__ __forceinline__ void ldm_x4(uint32_t* r, uint32_t addr) {
    asm volatile("ldmatrix.sync.aligned.m8n8.x4.shared.b16 {%0,%1,%2,%3}, [%4];"
                 : "=r"(r[0]), "=r"(r[1]), "=r"(r[2]), "=r"(r[3]) : "r"(addr));
}
__device__ __forceinline__ void mma_bf16(float* c, const uint32_t* a, const uint32_t* b) {
    asm volatile("mma.sync.aligned.m16n8k16.row.col.f32.bf16.bf16.f32 "
                 "{%0,%1,%2,%3}, {%4,%5,%6,%7}, {%8,%9}, {%0,%1,%2,%3};"
                 : "+f"(c[0]), "+f"(c[1]), "+f"(c[2]), "+f"(c[3])
                 : "r"(a[0]), "r"(a[1]), "r"(a[2]), "r"(a[3]), "r"(b[0]), "r"(b[1]));
}

// ---------------- init ----------------
__global__ void k_init() {
    int i = blockIdx.x * blockDim.x + threadIdx.x;
    if (i < BB * HH) { g_hbuf[0][i] = 0.f; g_cbuf[0][i] = 0.f; }
}

// ============ split W_out / Hall into bf16 hi/lo ============
__global__ void k_splitW(const float* __restrict__ W) {
    size_t i = (size_t)blockIdx.x * blockDim.x + threadIdx.x;
    if (i < (size_t)VV * HH) {
        float w = W[i];
        __nv_bfloat16 hi = __float2bfloat16_rn(w);
        __nv_bfloat16 lo = __float2bfloat16_rn(w - __bfloat162float(hi));
        g_Wh[i] = hi; g_Wl[i] = lo;
    }
}
__global__ void k_splitA() {
    int i = blockIdx.x * blockDim.x + threadIdx.x;
    if (i < BB * TT * HH) {
        float w = g_Hall[i];
        __nv_bfloat16 hi = __float2bfloat16_rn(w);
        __nv_bfloat16 lo = __float2bfloat16_rn(w - __bfloat162float(hi));
        g_Ah[i] = hi; g_Al[i] = lo;
    }
}

// ============ P = emb @ W_ih[:, 0:H].T + b_ih + b_hh ============
#define GBM 128
#define GBN 128
#define GBK 8

__global__ __launch_bounds__(256, 2) void k_embW(const int* __restrict__ captions,
                                                 const float* __restrict__ emb_table,
                                                 const float* __restrict__ W_ih,
                                                 const float* __restrict__ b_ih,
                                                 const float* __restrict__ b_hh) {
    __shared__ float As[GBK][GBM];
    __shared__ float Bs[GBK][GBN];
    int bm = blockIdx.x, bn = blockIdx.y;
    int tid = threadIdx.x;
    int l_row = tid >> 1, l_col = (tid & 1) * 4;
    int tx = tid & 15, ty = tid >> 4;

    int cap = captions[bm * GBM + l_row];
    const float* Arow = emb_table + (size_t)cap * HH;
    const float* Brow = W_ih + (size_t)(bn * GBN + l_row) * (2 * HH);

    float acc[8][8];
#pragma unroll
    for (int i = 0; i < 8; i++)
#pragma unroll
        for (int jj = 0; jj < 8; jj++) acc[i][jj] = 0.f;

    for (int k0 = 0; k0 < HH; k0 += GBK) {
        float4 av = *(const float4*)(Arow + k0 + l_col);
        As[l_col + 0][l_row] = av.x; As[l_col + 1][l_row] = av.y;
        As[l_col + 2][l_row] = av.z; As[l_col + 3][l_row] = av.w;
        float4 bv = *(const float4*)(Brow + k0 + l_col);
        Bs[l_col + 0][l_row] = bv.x; Bs[l_col + 1][l_row] = bv.y;
        Bs[l_col + 2][l_row] = bv.z; Bs[l_col + 3][l_row] = bv.w;
        __syncthreads();
#pragma unroll
        for (int kk = 0; kk < GBK; kk++) {
            float ar[8], br[8];
#pragma unroll
            for (int i = 0; i < 8; i++) ar[i] = As[kk][ty * 8 + i];
#pragma unroll
            for (int jj = 0; jj < 8; jj++) br[jj] = Bs[kk][tx * 8 + jj];
#pragma unroll
            for (int i = 0; i < 8; i++)
#pragma unroll
                for (int jj = 0; jj < 8; jj++) acc[i][jj] += ar[i] * br[jj];
        }
        __syncthreads();
    }
#pragma unroll
    for (int i = 0; i < 8; i++) {
        int m = bm * GBM + ty * 8 + i;
#pragma unroll
        for (int jj = 0; jj < 8; jj++) {
            int n = bn * GBN + tx * 8 + jj;
            g_P[(size_t)m * (4 * HH) + n] = acc[i][jj] + b_ih[n] + b_hh[n];
        }
    }
}

// ============ q partial ============
__global__ void k_q(const float* __restrict__ attn_W, int p) {
    int nt = blockIdx.x, ks = blockIdx.y;
    int kbeg = ks * 128;
    int tid = threadIdx.x, warp = tid >> 5, lane = tid & 31;
    __shared__ float xs[32][33];
    __shared__ float ws[32][68];
    float acc[16];
#pragma unroll
    for (int i = 0; i < 16; i++) acc[i] = 0.f;
    int jbase = nt * 64;

    for (int k0 = 0; k0 < 128; k0 += 32) {
        for (int i = tid; i < 1024; i += 128) {
            int m = i >> 5, kk = i & 31;
            xs[m][kk] = g_hbuf[p][m * HH + kbeg + k0 + kk];
        }
        for (int i = tid; i < 512; i += 128) {
            int j = i >> 3, k4 = (i & 7) * 4;
            float4 v = *(const float4*)(attn_W + (size_t)(jbase + j) * HH + kbeg + k0 + k4);
            ws[k4 + 0][j] = v.x; ws[k4 + 1][j] = v.y; ws[k4 + 2][j] = v.z; ws[k4 + 3][j] = v.w;
        }
        __syncthreads();
#pragma unroll
        for (int kk = 0; kk < 32; kk++) {
            float xv = xs[lane][kk];
            float4 w0 = *(const float4*)&ws[kk][warp * 16 + 0];
            float4 w1 = *(const float4*)&ws[kk][warp * 16 + 4];
            float4 w2 = *(const float4*)&ws[kk][warp * 16 + 8];
            float4 w3 = *(const float4*)&ws[kk][warp * 16 + 12];
            acc[0] += xv * w0.x; acc[1] += xv * w0.y; acc[2] += xv * w0.z; acc[3] += xv * w0.w;
            acc[4] += xv * w1.x; acc[5] += xv * w1.y; acc[6] += xv * w1.z; acc[7] += xv * w1.w;
            acc[8] += xv * w2.x; acc[9] += xv * w2.y; acc[10] += xv * w2.z; acc[11] += xv * w2.w;
            acc[12] += xv * w3.x; acc[13] += xv * w3.y; acc[14] += xv * w3.z; acc[15] += xv * w3.w;
        }
        __syncthreads();
    }
#pragma unroll
    for (int jj = 0; jj < 16; jj++)
        g_qpart[ks][lane * HH + jbase + warp * 16 + jj] = acc[jj];
}

__global__ void k_qred() {
    int i = blockIdx.x * blockDim.x + threadIdx.x;
    float s = 0.f;
#pragma unroll
    for (int ks = 0; ks < 8; ks++) s += g_qpart[ks][i];
    g_q[i] = s;
}

// ============ scores ============
__global__ void k_scores(const float* __restrict__ memory) {
    int b = blockIdx.y;
    int tid = threadIdx.x, warp = tid >> 5, lane = tid & 31;
    __shared__ float qs[HH];
    for (int i = tid; i < HH; i += 128) qs[i] = g_q[b * HH + i];
    __syncthreads();
    int s = blockIdx.x * 4 + warp;
    const float* mr = memory + ((size_t)b * SS + s) * HH;
    float a0 = 0.f, a1 = 0.f, a2 = 0.f, a3 = 0.f;
#pragma unroll 2
    for (int k0 = 0; k0 < HH; k0 += 128) {
        float m0 = mr[k0 + lane], m1 = mr[k0 + 32 + lane];
        float m2 = mr[k0 + 64 + lane], m3 = mr[k0 + 96 + lane];
        a0 += qs[k0 + lane] * m0;
        a1 += qs[k0 + 32 + lane] * m1;
        a2 += qs[k0 + 64 + lane] * m2;
        a3 += qs[k0 + 96 + lane] * m3;
    }
    float acc = a0 + a1 + a2 + a3;
#pragma unroll
    for (int o = 16; o > 0; o >>= 1) acc += __shfl_xor_sync(0xffffffffu, acc, o);
    if (lane == 0) g_sc[b * SS + s] = acc;
}

// ============ softmax + ctx ============
__global__ void k_ctx2(const float* __restrict__ memory) {
    int b = blockIdx.y;
    int tid = threadIdx.x;
    __shared__ float w[SS];
    __shared__ float red[256];

    float v = (tid < SS) ? g_sc[b * SS + tid] : -1e30f;
    red[tid] = v;
    __syncthreads();
    for (int o = 128; o > 0; o >>= 1) {
        if (tid < o) red[tid] = fmaxf(red[tid], red[tid + o]);
        __syncthreads();
    }
    float mx = red[0];
    __syncthreads();
    float e = (tid < SS) ? expf(v - mx) : 0.f;
    if (tid < SS) w[tid] = e;
    red[tid] = e;
    __syncthreads();
    for (int o = 128; o > 0; o >>= 1) {
        if (tid < o) red[tid] += red[tid + o];
        __syncthreads();
    }
    float inv = 1.f / red[0];
    __syncthreads();

    int hcol = blockIdx.x * 256 + tid;
    const float* mb = memory + (size_t)b * SS * HH + hcol;
    float a0 = 0.f, a1 = 0.f, a2 = 0.f, a3 = 0.f;
    int s = 0;
    for (; s + 8 <= SS; s += 8) {
        float m0 = mb[(size_t)(s + 0) * HH], m1 = mb[(size_t)(s + 1) * HH];
        float m2 = mb[(size_t)(s + 2) * HH], m3 = mb[(size_t)(s + 3) * HH];
        float m4 = mb[(size_t)(s + 4) * HH], m5 = mb[(size_t)(s + 5) * HH];
        float m6 = mb[(size_t)(s + 6) * HH], m7 = mb[(size_t)(s + 7) * HH];
        a0 += w[s + 0] * m0; a1 += w[s + 1] * m1; a2 += w[s + 2] * m2; a3 += w[s + 3] * m3;
        a0 += w[s + 4] * m4; a1 += w[s + 5] * m5; a2 += w[s + 6] * m6; a3 += w[s + 7] * m7;
    }
    {
        float m0 = mb[(size_t)(s + 0) * HH], m1 = mb[(size_t)(s + 1) * HH];
        float m2 = mb[(size_t)(s + 2) * HH], m3 = mb[(size_t)(s + 3) * HH];
        a0 += w[s + 0] * m0; a1 += w[s + 1] * m1; a2 += w[s + 2] * m2; a3 += w[s + 3] * m3;
    }
    g_ctx[b * HH + hcol] = (a0 + a1 + a2 + a3) * inv;
}

// ============ gates partials ============
__global__ void k_gates_b(const float* __restrict__ W_ih,
                          const float* __restrict__ W_hh, int p) {
    int nt = blockIdx.x, ks = blockIdx.y;
    int kbeg = ks * 512;
    int tid = threadIdx.x, warp = tid >> 5, lane = tid & 31;
    __shared__ float xs[32][33];
    __shared__ float ws[32][68];

    const float* xbase;
    const float* wbase;
    int wstride;
    if (ks < 2) { xbase = g_ctx + kbeg;            wbase = W_ih + HH + kbeg; wstride = 2 * HH; }
    else        { xbase = g_hbuf[p] + (kbeg - HH); wbase = W_hh + (kbeg - HH); wstride = HH; }

    float acc[16];
#pragma unroll
    for (int i = 0; i < 16; i++) acc[i] = 0.f;
    int jbase = nt * 64;

    for (int k0 = 0; k0 < 512; k0 += 32) {
        for (int i = tid; i < 1024; i += 128) {
            int m = i >> 5, kk = i & 31;
            xs[m][kk] = xbase[m * HH + k0 + kk];
        }
        for (int i = tid; i < 512; i += 128) {
            int j = i >> 3, k4 = (i & 7) * 4;
            float4 v = *(const float4*)(wbase + (size_t)(jbase + j) * wstride + k0 + k4);
            ws[k4 + 0][j] = v.x; ws[k4 + 1][j] = v.y; ws[k4 + 2][j] = v.z; ws[k4 + 3][j] = v.w;
        }
        __syncthreads();
#pragma unroll
        for (int kk = 0; kk < 32; kk++) {
            float xv = xs[lane][kk];
            float4 w0 = *(const float4*)&ws[kk][warp * 16 + 0];
            float4 w1 = *(const float4*)&ws[kk][warp * 16 + 4];
            float4 w2 = *(const float4*)&ws[kk][warp * 16 + 8];
            float4 w3 = *(const float4*)&ws[kk][warp * 16 + 12];
            acc[0] += xv * w0.x; acc[1] += xv * w0.y; acc[2] += xv * w0.z; acc[3] += xv * w0.w;
            acc[4] += xv * w1.x; acc[5] += xv * w1.y; acc[6] += xv * w1.z; acc[7] += xv * w1.w;
            acc[8] += xv * w2.x; acc[9] += xv * w2.y; acc[10] += xv * w2.z; acc[11] += xv * w2.w;
            acc[12] += xv * w3.x; acc[13] += xv * w3.y; acc[14] += xv * w3.z; acc[15] += xv * w3.w;
        }
        __syncthreads();
    }
#pragma unroll
    for (int jj = 0; jj < 16; jj++)
        g_gpart[ks][lane * (4 * HH) + jbase + warp * 16 + jj] = acc[jj];
}

// ============ LSTM cell ============
__global__ void k_cell(int t, int p) {
    int i = blockIdx.x * blockDim.x + threadIdx.x;
    int b = i >> 10, j = i & 1023;
    size_t pr = (size_t)(b * TT + t) * (4 * HH);
    float a0 = g_P[pr + j];
    float a1 = g_P[pr + j + HH];
    float a2 = g_P[pr + j + 2 * HH];
    float a3 = g_P[pr + j + 3 * HH];
#pragma unroll
    for (int ks = 0; ks < 4; ks++) {
        const float* gp = g_gpart[ks] + b * (4 * HH);
        a0 += gp[j];
        a1 += gp[j + HH];
        a2 += gp[j + 2 * HH];
        a3 += gp[j + 3 * HH];
    }
    float gi = sigmoidf_(a0);
    float gf = sigmoidf_(a1);
    float gg = tanhf(a2);
    float go = sigmoidf_(a3);
    float cp = g_cbuf[p][b * HH + j];
    float cn = gf * cp + gi * gg;
    float hn = go * tanhf(cn);
    g_cbuf[p ^ 1][b * HH + j] = cn;
    g_hbuf[p ^ 1][b * HH + j] = hn;
    g_Hall[(b * TT + t) * HH + j] = hn;
}

// ============ HMMA logits GEMM ============
// D[2048,32000] = Ah·Bh^T + Ah·Bl^T + Al·Bh^T + bias
// 128x128x64 tiles, cp.async 2-stage pipe, mma.sync m16n8k16 bf16.
#define LPITCH 72                         // bf16 per smem row (144 B = 9 x 16B -> conflict-free)
#define LTILE (128 * LPITCH * 2)          // 18432 B
#define LSTAGE (4 * LTILE)                // 73728 B (Ah, Al, Bh, Bl)
#define LSMEM (2 * LSTAGE)                // 147456 B

__global__ __launch_bounds__(256, 1) void k_logits_mma(const float* __restrict__ bout,
                                                       float* __restrict__ out) {
    extern __shared__ char smem[];
    uint32_t sb = smem_u32(smem);
    int tid = threadIdx.x, wid = tid >> 5, lane = tid & 31;
    int wm = wid >> 2, wn = wid & 3;      // 2 x 4 warp grid, warp tile 64 x 32
    int bm = blockIdx.x, bn = blockIdx.y;

    const __nv_bfloat16* gA[4];
    gA[0] = g_Ah + (size_t)bm * 128 * HH;
    gA[1] = g_Al + (size_t)bm * 128 * HH;
    gA[2] = g_Wh + (size_t)bn * 128 * HH;
    gA[3] = g_Wl + (size_t)bn * 128 * HH;

    float acc[4][4][4];
#pragma unroll
    for (int i = 0; i < 4; i++)
#pragma unroll
        for (int j = 0; j < 4; j++)
#pragma unroll
            for (int k = 0; k < 4; k++) acc[i][j][k] = 0.f;

    int lrow = tid >> 3;                  // 0..31 base row (x4 stacked)
    int lc4 = tid & 7;                    // 16B chunk in row

    // issue chunk 0 -> stage 0
    {
        int k0 = 0;
#pragma unroll
        for (int t = 0; t < 4; t++) {
            uint32_t base = sb + t * LTILE;
#pragma unroll
            for (int r4 = 0; r4 < 4; r4++) {
                int row = lrow + r4 * 32;
                cp16(base + row * 144 + lc4 * 16, gA[t] + (size_t)row * HH + k0 + lc4 * 8);
            }
        }
        asm volatile("cp.async.commit_group;");
    }

    for (int ch = 0; ch < 16; ch++) {
        int st = ch & 1;
        if (ch < 15) {
            int k0 = (ch + 1) * 64;
            uint32_t stb = sb + ((ch + 1) & 1) * LSTAGE;
#pragma unroll
            for (int t = 0; t < 4; t++) {
                uint32_t base = stb + t * LTILE;
#pragma unroll
                for (int r4 = 0; r4 < 4; r4++) {
                    int row = lrow + r4 * 32;
                    cp16(base + row * 144 + lc4 * 16, gA[t] + (size_t)row * HH + k0 + lc4 * 8);
                }
            }
            asm volatile("cp.async.commit_group;");
            asm volatile("cp.async.wait_group 1;");
        } else {
            asm volatile("cp.async.wait_group 0;");
        }
        __syncthreads();

        uint32_t sAh = sb + st * LSTAGE;
        uint32_t sAl = sAh + LTILE;
        uint32_t sBh = sAh + 2 * LTILE;
        uint32_t sBl = sAh + 3 * LTILE;

#pragma unroll
        for (int k16 = 0; k16 < 4; k16++) {
            int kc = k16 * 16;
            // B fragments: rows are n, ldmatrix no-trans gives col-major B frags
            uint32_t bh[4][2], bl[4][2];
#pragma unroll
            for (int j2 = 0; j2 < 2; j2++) {
                int nrow = wn * 32 + j2 * 16 + ((lane >> 4) << 3) + (lane & 7);
                int kcol = kc + (lane & 8);
                uint32_t r[4];
                ldm_x4(r, sBh + nrow * 144 + kcol * 2);
                bh[j2 * 2][0] = r[0]; bh[j2 * 2][1] = r[1];
                bh[j2 * 2 + 1][0] = r[2]; bh[j2 * 2 + 1][1] = r[3];
                ldm_x4(r, sBl + nrow * 144 + kcol * 2);
                bl[j2 * 2][0] = r[0]; bl[j2 * 2][1] = r[1];
                bl[j2 * 2 + 1][0] = r[2]; bl[j2 * 2 + 1][1] = r[3];
            }
#pragma unroll
            for (int i = 0; i < 4; i++) {
                int arow = wm * 64 + i * 16 + (lane & 15);
                int acol = kc + ((lane >> 4) << 3);
                uint32_t ah[4], al[4];
                ldm_x4(ah, sAh + arow * 144 + acol * 2);
                ldm_x4(al, sAl + arow * 144 + acol * 2);
#pragma unroll
                for (int j = 0; j < 4; j++) mma_bf16(acc[i][j], ah, bh[j]);
#pragma unroll
                for (int j = 0; j < 4; j++) mma_bf16(acc[i][j], ah, bl[j]);
#pragma unroll
                for (int j = 0; j < 4; j++) mma_bf16(acc[i][j], al, bh[j]);
            }
        }
        __syncthreads();
    }

    // epilogue
#pragma unroll
    for (int i = 0; i < 4; i++) {
        int row0 = bm * 128 + wm * 64 + i * 16 + (lane >> 2);
#pragma unroll
        for (int j = 0; j < 4; j++) {
            int col = bn * 128 + wn * 32 + j * 8 + (lane & 3) * 2;
            float2 bv = *(const float2*)(bout + col);
            float2 o0 = make_float2(acc[i][j][0] + bv.x, acc[i][j][1] + bv.y);
            float2 o1 = make_float2(acc[i][j][2] + bv.x, acc[i][j][3] + bv.y);
            *(float2*)(out + (size_t)row0 * VV + col) = o0;
            *(float2*)(out + (size_t)(row0 + 8) * VV + col) = o1;
        }
    }
}

// ============ final h, c ============
__global__ void k_final(float* __restrict__ out) {
    int i = blockIdx.x * blockDim.x + threadIdx.x;
    if (i < BB * HH) {
        size_t base = (size_t)BB * TT * VV;
        out[base + i] = g_hbuf[0][i];
        out[base + BB * HH + i] = g_cbuf[0][i];
    }
}

// ---------------- launch ----------------
extern "C" void kernel_launch(void* const* d_in, const int* in_sizes, int n_in,
                              void* d_out, int out_size) {
    const float* memory    = (const float*)d_in[0];
    const int*   captions  = (const int*)d_in[1];
    const float* emb_table = (const float*)d_in[2];
    const float* attn_W    = (const float*)d_in[3];
    const float* W_ih      = (const float*)d_in[4];
    const float* W_hh      = (const float*)d_in[5];
    const float* b_ih      = (const float*)d_in[6];
    const float* b_hh      = (const float*)d_in[7];
    const float* W_out     = (const float*)d_in[8];
    const float* b_out     = (const float*)d_in[9];
    float* out = (float*)d_out;

    static int smem_set = 0;
    if (!smem_set) {
        cudaFuncSetAttribute(k_logits_mma, cudaFuncAttributeMaxDynamicSharedMemorySize, LSMEM);
        smem_set = 1;
    }

    k_init<<<(BB * HH + 255) / 256, 256>>>();
    k_embW<<<dim3((BB * TT) / GBM, (4 * HH) / GBN), 256>>>(captions, emb_table, W_ih, b_ih, b_hh);
    k_splitW<<<(int)(((size_t)VV * HH + 255) / 256), 256>>>(W_out);

    for (int t = 0; t < TT; t++) {
        int p = t & 1;
        k_q<<<dim3(16, 8), 128>>>(attn_W, p);
        k_qred<<<128, 256>>>();
        k_scores<<<dim3(49, BB), 128>>>(memory);
        k_ctx2<<<dim3(4, BB), 256>>>(memory);
        k_gates_b<<<dim3(64, 4), 128>>>(W_ih, W_hh, p);
        k_cell<<<128, 256>>>(t, p);
    }

    k_splitA<<<(BB * TT * HH + 255) / 256, 256>>>();
    k_logits_mma<<<dim3(16, VV / 128), 256, LSMEM>>>(b_out, out);
    k_final<<<(BB * HH + 255) / 256, 256>>>(out);
}

// round 5
// speedup vs baseline: 4.6881x; 1.9786x over previous
#include <cuda_runtime.h>
#include <cuda_bf16.h>
#include <math.h>
#include <stdint.h>

#define BB 32
#define SS 196
#define TT 64
#define HH 1024
#define VV 32000
#define MT (BB * TT)     // 2048
#define KG 2048          // gates K
#define NG 4096          // gates N

// ---------------- device scratch ----------------
__device__ float g_h[BB * HH];
__device__ float g_c[BB * HH];
__device__ float g_sc[BB * SS];
__device__ float g_M2[(size_t)BB * SS * HH];
__device__ float g_P[(size_t)MT * NG];
__device__ float g_gpart[(size_t)8 * BB * NG];
__device__ float g_biasg[NG];
__device__ float g_zeroN[VV];
__device__ __nv_bfloat16 g_Wh[(size_t)VV * HH], g_Wl[(size_t)VV * HH];
__device__ __nv_bfloat16 g_Ah[(size_t)MT * HH], g_Al[(size_t)MT * HH];
__device__ __nv_bfloat16 g_Memh[(size_t)BB * SS * HH], g_Meml[(size_t)BB * SS * HH];
__device__ __nv_bfloat16 g_Wth[(size_t)HH * HH], g_Wtl[(size_t)HH * HH];
__device__ __nv_bfloat16 g_WihAh[(size_t)NG * HH], g_WihAl[(size_t)NG * HH];
__device__ __nv_bfloat16 g_Wgh[(size_t)NG * KG], g_Wgl[(size_t)NG * KG];
__device__ __nv_bfloat16 g_Embh[(size_t)MT * HH], g_Embl[(size_t)MT * HH];
__device__ __nv_bfloat16 g_Xh[128 * KG], g_Xl[128 * KG];

__device__ __forceinline__ float sigmoidf_(float x) { return 1.f / (1.f + expf(-x)); }
__device__ __forceinline__ void bsplit(float w, __nv_bfloat16& hi, __nv_bfloat16& lo) {
    hi = __float2bfloat16_rn(w);
    lo = __float2bfloat16_rn(w - __bfloat162float(hi));
}

__device__ __forceinline__ uint32_t smem_u32(const void* p) {
    uint32_t a;
    asm("{ .reg .u64 t; cvta.to.shared.u64 t, %1; cvt.u32.u64 %0, t; }" : "=r"(a) : "l"(p));
    return a;
}
__device__ __forceinline__ void cp16(uint32_t s, const void* g) {
    asm volatile("cp.async.cg.shared.global [%0], [%1], 16;" :: "r"(s), "l"(g));
}
__device__ __forceinline__ void ldm_x4(uint32_t* r, uint32_t addr) {
    asm volatile("ldmatrix.sync.aligned.m8n8.x4.shared.b16 {%0,%1,%2,%3}, [%4];"
                 : "=r"(r[0]), "=r"(r[1]), "=r"(r[2]), "=r"(r[3]) : "r"(addr));
}
__device__ __forceinline__ void mma_bf16(float* c, const uint32_t* a, const uint32_t* b) {
    asm volatile("mma.sync.aligned.m16n8k16.row.col.f32.bf16.bf16.f32 "
                 "{%0,%1,%2,%3}, {%4,%5,%6,%7}, {%8,%9}, {%0,%1,%2,%3};"
                 : "+f"(c[0]), "+f"(c[1]), "+f"(c[2]), "+f"(c[3])
                 : "r"(a[0]), "r"(a[1]), "r"(a[2]), "r"(a[3]), "r"(b[0]), "r"(b[1]));
}

// ================= init / split kernels =================
__global__ void k_init(const float* __restrict__ b_ih, const float* __restrict__ b_hh) {
    int i = blockIdx.x * blockDim.x + threadIdx.x;   // grid covers 128*KG = 262144
    __nv_bfloat16 z = __float2bfloat16(0.f);
    if (i < 128 * KG) { g_Xh[i] = z; g_Xl[i] = z; }
    if (i < BB * HH) { g_h[i] = 0.f; g_c[i] = 0.f; }
    if (i < VV) g_zeroN[i] = 0.f;
    if (i < NG) g_biasg[i] = b_ih[i] + b_hh[i];
}

__global__ void k_splitW(const float* __restrict__ W) {
    size_t i = (size_t)blockIdx.x * blockDim.x + threadIdx.x;
    if (i < (size_t)VV * HH) bsplit(W[i], g_Wh[i], g_Wl[i]);
}
__global__ void k_splitWg(const float* __restrict__ W_ih, const float* __restrict__ W_hh) {
    size_t i = (size_t)blockIdx.x * blockDim.x + threadIdx.x;
    if (i < (size_t)NG * KG) {
        size_t n = i >> 11;
        int k = (int)(i & 2047);
        float w = (k < HH) ? W_ih[n * (2 * HH) + HH + k] : W_hh[n * HH + (k - HH)];
        bsplit(w, g_Wgh[i], g_Wgl[i]);
    }
}
__global__ void k_splitWihA(const float* __restrict__ W_ih) {
    size_t i = (size_t)blockIdx.x * blockDim.x + threadIdx.x;
    if (i < (size_t)NG * HH) {
        size_t n = i >> 10;
        int k = (int)(i & 1023);
        bsplit(W_ih[n * (2 * HH) + k], g_WihAh[i], g_WihAl[i]);
    }
}
__global__ void k_splitMem(const float* __restrict__ memory) {
    size_t i = (size_t)blockIdx.x * blockDim.x + threadIdx.x;
    if (i < (size_t)BB * SS * HH) bsplit(memory[i], g_Memh[i], g_Meml[i]);
}
__global__ void k_splitEmb(const int* __restrict__ captions, const float* __restrict__ emb_table) {
    size_t i = (size_t)blockIdx.x * blockDim.x + threadIdx.x;
    if (i < (size_t)MT * HH) {
        int m = (int)(i >> 10);
        int k = (int)(i & 1023);
        bsplit(emb_table[(size_t)captions[m] * HH + k], g_Embh[i], g_Embl[i]);
    }
}
// Wt[n][j] = attn_W[j][n]
__global__ void k_splitWt(const float* __restrict__ W) {
    __shared__ float tile[32][33];
    int jb = blockIdx.x * 32, nb = blockIdx.y * 32;
    int tx = threadIdx.x & 31, ty = threadIdx.x >> 5;   // 32 x 8
#pragma unroll
    for (int r = 0; r < 32; r += 8)
        tile[ty + r][tx] = W[(size_t)(jb + ty + r) * HH + nb + tx];
    __syncthreads();
#pragma unroll
    for (int r = 0; r < 32; r += 8) {
        size_t o = (size_t)(nb + ty + r) * HH + jb + tx;
        bsplit(tile[tx][ty + r], g_Wth[o], g_Wtl[o]);
    }
}

// ================= generic 3-pass HMMA GEMM core =================
// out[m,n] = sum_k A[m,k]*B[n,k] (hi/lo split, 3 passes) + bias[n]
// BM=BN=128, K chunks of 64, cp.async 2-stage, 8 warps (2x4), warp tile 64x32.
#define LPITCH 72
#define LTILE (128 * LPITCH * 2)    // 18432 B
#define LSTAGE (4 * LTILE)          // 73728 B
#define LSMEM (2 * LSTAGE)          // 147456 B

__device__ __forceinline__ void gemm_core(
    const __nv_bfloat16* __restrict__ Ah, const __nv_bfloat16* __restrict__ Al,
    const __nv_bfloat16* __restrict__ Bh, const __nv_bfloat16* __restrict__ Bl,
    const float* __restrict__ bias, float* __restrict__ out,
    size_t ldout, int Ktot, int mlimit, size_t pstride)
{
    extern __shared__ char smem[];
    uint32_t sb = smem_u32(smem);
    int tid = threadIdx.x, wid = tid >> 5, lane = tid & 31;
    int wm = wid >> 2, wn = wid & 3;
    int bm = blockIdx.x, bn = blockIdx.y, ks = blockIdx.z;
    int Kper = Ktot / (int)gridDim.z;
    int chunks = Kper >> 6;
    int kbeg = ks * Kper;

    const __nv_bfloat16* gA[4];
    gA[0] = Ah + (size_t)bm * 128 * Ktot + kbeg;
    gA[1] = Al + (size_t)bm * 128 * Ktot + kbeg;
    gA[2] = Bh + (size_t)bn * 128 * Ktot + kbeg;
    gA[3] = Bl + (size_t)bn * 128 * Ktot + kbeg;

    float acc[4][4][4];
#pragma unroll
    for (int i = 0; i < 4; i++)
#pragma unroll
        for (int j = 0; j < 4; j++)
#pragma unroll
            for (int k = 0; k < 4; k++) acc[i][j][k] = 0.f;

    int lrow = tid >> 3;
    int lc4 = tid & 7;

    // prologue: chunk 0 -> stage 0
#pragma unroll
    for (int t = 0; t < 4; t++) {
        uint32_t base = sb + t * LTILE;
#pragma unroll
        for (int r4 = 0; r4 < 4; r4++) {
            int row = lrow + r4 * 32;
            cp16(base + row * 144 + lc4 * 16, gA[t] + (size_t)row * Ktot + lc4 * 8);
        }
    }
    asm volatile("cp.async.commit_group;");

    for (int ch = 0; ch < chunks; ch++) {
        int st = ch & 1;
        if (ch < chunks - 1) {
            int k0 = (ch + 1) * 64;
            uint32_t stb = sb + ((ch + 1) & 1) * LSTAGE;
#pragma unroll
            for (int t = 0; t < 4; t++) {
                uint32_t base = stb + t * LTILE;
#pragma unroll
                for (int r4 = 0; r4 < 4; r4++) {
                    int row = lrow + r4 * 32;
                    cp16(base + row * 144 + lc4 * 16, gA[t] + (size_t)row * Ktot + k0 + lc4 * 8);
                }
            }
            asm volatile("cp.async.commit_group;");
            asm volatile("cp.async.wait_group 1;");
        } else {
            asm volatile("cp.async.wait_group 0;");
        }
        __syncthreads();

        uint32_t sAh = sb + st * LSTAGE;
        uint32_t sAl = sAh + LTILE;
        uint32_t sBh = sAh + 2 * LTILE;
        uint32_t sBl = sAh + 3 * LTILE;

#pragma unroll
        for (int k16 = 0; k16 < 4; k16++) {
            int kc = k16 * 16;
            uint32_t bh[4][2], bl[4][2];
#pragma unroll
            for (int j2 = 0; j2 < 2; j2++) {
                int nrow = wn * 32 + j2 * 16 + ((lane >> 4) << 3) + (lane & 7);
                int kcol = kc + (lane & 8);
                uint32_t r[4];
                ldm_x4(r, sBh + nrow * 144 + kcol * 2);
                bh[j2 * 2][0] = r[0]; bh[j2 * 2][1] = r[1];
                bh[j2 * 2 + 1][0] = r[2]; bh[j2 * 2 + 1][1] = r[3];
                ldm_x4(r, sBl + nrow * 144 + kcol * 2);
                bl[j2 * 2][0] = r[0]; bl[j2 * 2][1] = r[1];
                bl[j2 * 2 + 1][0] = r[2]; bl[j2 * 2 + 1][1] = r[3];
            }
#pragma unroll
            for (int i = 0; i < 4; i++) {
                int arow = wm * 64 + i * 16 + (lane & 15);
                int acol = kc + ((lane >> 4) << 3);
                uint32_t ah[4], al[4];
                ldm_x4(ah, sAh + arow * 144 + acol * 2);
                ldm_x4(al, sAl + arow * 144 + acol * 2);
#pragma unroll
                for (int j = 0; j < 4; j++) mma_bf16(acc[i][j], ah, bh[j]);
#pragma unroll
                for (int j = 0; j < 4; j++) mma_bf16(acc[i][j], ah, bl[j]);
#pragma unroll
                for (int j = 0; j < 4; j++) mma_bf16(acc[i][j], al, bh[j]);
            }
        }
        __syncthreads();
    }

    float* outp = out + (size_t)ks * pstride;
#pragma unroll
    for (int i = 0; i < 4; i++) {
        int row0 = bm * 128 + wm * 64 + i * 16 + (lane >> 2);
#pragma unroll
        for (int j = 0; j < 4; j++) {
            int col = bn * 128 + wn * 32 + j * 8 + (lane & 3) * 2;
            float2 bv = *(const float2*)(bias + col);
            if (row0 < mlimit) {
                float2 o0 = make_float2(acc[i][j][0] + bv.x, acc[i][j][1] + bv.y);
                *(float2*)(outp + (size_t)row0 * ldout + col) = o0;
            }
            if (row0 + 8 < mlimit) {
                float2 o1 = make_float2(acc[i][j][2] + bv.x, acc[i][j][3] + bv.y);
                *(float2*)(outp + (size_t)(row0 + 8) * ldout + col) = o1;
            }
        }
    }
}

// instantiations
__global__ __launch_bounds__(256, 1) void k_gemm_M2() {
    gemm_core(g_Memh, g_Meml, g_Wth, g_Wtl, g_zeroN, g_M2, HH, HH, 1 << 30, 0);
}
__global__ __launch_bounds__(256, 1) void k_gemm_P() {
    gemm_core(g_Embh, g_Embl, g_WihAh, g_WihAl, g_biasg, g_P, NG, HH, 1 << 30, 0);
}
__global__ __launch_bounds__(256, 1) void k_gemm_G() {
    gemm_core(g_Xh, g_Xl, g_Wgh, g_Wgl, g_zeroN, g_gpart, NG, KG, BB, (size_t)BB * NG);
}
__global__ __launch_bounds__(256, 1) void k_gemm_L(const float* __restrict__ bout,
                                                   float* __restrict__ out) {
    gemm_core(g_Ah, g_Al, g_Wh, g_Wl, bout, out, VV, HH, 1 << 30, 0);
}

// ================= per-step kernels =================
// scores[b,s] = h[b,:] . M2[b*SS+s, :]   grid(49, BB), 128 thr
__global__ void k_scores2() {
    int b = blockIdx.y;
    int tid = threadIdx.x, warp = tid >> 5, lane = tid & 31;
    __shared__ float hs[HH];
    for (int i = tid; i < HH; i += 128) hs[i] = g_h[b * HH + i];
    __syncthreads();
    int s = blockIdx.x * 4 + warp;
    const float* mr = g_M2 + ((size_t)b * SS + s) * HH;
    float a0 = 0.f, a1 = 0.f, a2 = 0.f, a3 = 0.f;
#pragma unroll 2
    for (int k0 = 0; k0 < HH; k0 += 128) {
        float m0 = mr[k0 + lane], m1 = mr[k0 + 32 + lane];
        float m2 = mr[k0 + 64 + lane], m3 = mr[k0 + 96 + lane];
        a0 += hs[k0 + lane] * m0;
        a1 += hs[k0 + 32 + lane] * m1;
        a2 += hs[k0 + 64 + lane] * m2;
        a3 += hs[k0 + 96 + lane] * m3;
    }
    float acc = a0 + a1 + a2 + a3;
#pragma unroll
    for (int o = 16; o > 0; o >>= 1) acc += __shfl_xor_sync(0xffffffffu, acc, o);
    if (lane == 0) g_sc[b * SS + s] = acc;
}

// softmax + ctx; writes bf16 split of ctx into X[:, 0:H].  grid(4, BB), 256 thr
__global__ void k_ctx2(const float* __restrict__ memory) {
    int b = blockIdx.y;
    int tid = threadIdx.x;
    __shared__ float w[SS];
    __shared__ float red[256];

    float v = (tid < SS) ? g_sc[b * SS + tid] : -1e30f;
    red[tid] = v;
    __syncthreads();
    for (int o = 128; o > 0; o >>= 1) {
        if (tid < o) red[tid] = fmaxf(red[tid], red[tid + o]);
        __syncthreads();
    }
    float mx = red[0];
    __syncthreads();
    float e = (tid < SS) ? expf(v - mx) : 0.f;
    if (tid < SS) w[tid] = e;
    red[tid] = e;
    __syncthreads();
    for (int o = 128; o > 0; o >>= 1) {
        if (tid < o) red[tid] += red[tid + o];
        __syncthreads();
    }
    float inv = 1.f / red[0];
    __syncthreads();

    int hcol = blockIdx.x * 256 + tid;
    const float* mb = memory + (size_t)b * SS * HH + hcol;
    float a0 = 0.f, a1 = 0.f, a2 = 0.f, a3 = 0.f;
    int s = 0;
    for (; s + 8 <= SS; s += 8) {
        float m0 = mb[(size_t)(s + 0) * HH], m1 = mb[(size_t)(s + 1) * HH];
        float m2 = mb[(size_t)(s + 2) * HH], m3 = mb[(size_t)(s + 3) * HH];
        float m4 = mb[(size_t)(s + 4) * HH], m5 = mb[(size_t)(s + 5) * HH];
        float m6 = mb[(size_t)(s + 6) * HH], m7 = mb[(size_t)(s + 7) * HH];
        a0 += w[s + 0] * m0; a1 += w[s + 1] * m1; a2 += w[s + 2] * m2; a3 += w[s + 3] * m3;
        a0 += w[s + 4] * m4; a1 += w[s + 5] * m5; a2 += w[s + 6] * m6; a3 += w[s + 7] * m7;
    }
    {
        float m0 = mb[(size_t)(s + 0) * HH], m1 = mb[(size_t)(s + 1) * HH];
        float m2 = mb[(size_t)(s + 2) * HH], m3 = mb[(size_t)(s + 3) * HH];
        a0 += w[s + 0] * m0; a1 += w[s + 1] * m1; a2 += w[s + 2] * m2; a3 += w[s + 3] * m3;
    }
    float cv = (a0 + a1 + a2 + a3) * inv;
    __nv_bfloat16 hi, lo;
    bsplit(cv, hi, lo);
    g_Xh[b * KG + hcol] = hi;
    g_Xl[b * KG + hcol] = lo;
}

// LSTM cell: reduce 8 gate partials + P, activations, write h (fp32 + bf16 splits)
__global__ void k_cell(int t) {
    int i = blockIdx.x * blockDim.x + threadIdx.x;
    int b = i >> 10, j = i & 1023;
    size_t pr = ((size_t)b * TT + t) * NG;
    float a0 = g_P[pr + j];
    float a1 = g_P[pr + HH + j];
    float a2 = g_P[pr + 2 * HH + j];
    float a3 = g_P[pr + 3 * HH + j];
#pragma unroll
    for (int z = 0; z < 8; z++) {
        const float* gp = g_gpart + ((size_t)z * BB + b) * NG;
        a0 += gp[j];
        a1 += gp[HH + j];
        a2 += gp[2 * HH + j];
        a3 += gp[3 * HH + j];
    }
    float gi = sigmoidf_(a0);
    float gf = sigmoidf_(a1);
    float gg = tanhf(a2);
    float go = sigmoidf_(a3);
    float cp = g_c[i];
    float cn = gf * cp + gi * gg;
    float hn = go * tanhf(cn);
    g_c[i] = cn;
    g_h[i] = hn;
    __nv_bfloat16 hi, lo;
    bsplit(hn, hi, lo);
    g_Xh[b * KG + HH + j] = hi;
    g_Xl[b * KG + HH + j] = lo;
    size_t ar = ((size_t)b * TT + t) * HH + j;
    g_Ah[ar] = hi;
    g_Al[ar] = lo;
}

// ============ final h, c ============
__global__ void k_final(float* __restrict__ out) {
    int i = blockIdx.x * blockDim.x + threadIdx.x;
    if (i < BB * HH) {
        size_t base = (size_t)BB * TT * VV;
        out[base + i] = g_h[i];
        out[base + BB * HH + i] = g_c[i];
    }
}

// ---------------- launch ----------------
extern "C" void kernel_launch(void* const* d_in, const int* in_sizes, int n_in,
                              void* d_out, int out_size) {
    const float* memory    = (const float*)d_in[0];
    const int*   captions  = (const int*)d_in[1];
    const float* emb_table = (const float*)d_in[2];
    const float* attn_W    = (const float*)d_in[3];
    const float* W_ih      = (const float*)d_in[4];
    const float* W_hh      = (const float*)d_in[5];
    const float* b_ih      = (const float*)d_in[6];
    const float* b_hh      = (const float*)d_in[7];
    const float* W_out     = (const float*)d_in[8];
    const float* b_out     = (const float*)d_in[9];
    float* out = (float*)d_out;

    static int inited = 0;
    if (!inited) {
        cudaFuncSetAttribute(k_gemm_M2, cudaFuncAttributeMaxDynamicSharedMemorySize, LSMEM);
        cudaFuncSetAttribute(k_gemm_P,  cudaFuncAttributeMaxDynamicSharedMemorySize, LSMEM);
        cudaFuncSetAttribute(k_gemm_G,  cudaFuncAttributeMaxDynamicSharedMemorySize, LSMEM);
        cudaFuncSetAttribute(k_gemm_L,  cudaFuncAttributeMaxDynamicSharedMemorySize, LSMEM);
        inited = 1;
    }

    k_init<<<1024, 256>>>(b_ih, b_hh);
    k_splitW<<<(int)(((size_t)VV * HH + 255) / 256), 256>>>(W_out);
    k_splitWg<<<(int)(((size_t)NG * KG + 255) / 256), 256>>>(W_ih, W_hh);
    k_splitWihA<<<(int)(((size_t)NG * HH + 255) / 256), 256>>>(W_ih);
    k_splitMem<<<(int)(((size_t)BB * SS * HH + 255) / 256), 256>>>(memory);
    k_splitEmb<<<(int)(((size_t)MT * HH + 255) / 256), 256>>>(captions, emb_table);
    k_splitWt<<<dim3(HH / 32, HH / 32), 256>>>(attn_W);

    k_gemm_M2<<<dim3(BB * SS / 128, HH / 128, 1), 256, LSMEM>>>();
    k_gemm_P<<<dim3(MT / 128, NG / 128, 1), 256, LSMEM>>>();

    for (int t = 0; t < TT; t++) {
        k_scores2<<<dim3(49, BB), 128>>>();
        k_ctx2<<<dim3(4, BB), 256>>>(memory);
        k_gemm_G<<<dim3(1, NG / 128, 8), 256, LSMEM>>>();
        k_cell<<<128, 256>>>(t);
    }

    k_gemm_L<<<dim3(MT / 128, VV / 128, 1), 256, LSMEM>>>(b_out, out);
    k_final<<<128, 256>>>(out);
}